// round 14
// baseline (speedup 1.0000x reference)
#include <cuda_runtime.h>
#include <cuda_bf16.h>
#include <cstdint>

#define TT 2048
#define BB 32
#define HH 512
#define GG 2048            // 4*H
#define VOCAB 32000
#define NCOL 2             // batch columns
#define BPC 16             // batches per column
#define NRG 32             // CTAs per column per layer
#define NU 16              // hidden units per CTA
#define RT 288             // 8 MMA warps + 1 poller warp

// GEMM geometry (input projection, layer 0 only)
#define GM 128
#define GN 128
#define KC 64
#define RSB 144
#define STAGE 73728
#define OFF_A_HI 0
#define OFF_A_LO 18432
#define OFF_B_HI 36864
#define OFF_B_LO 55296
#define OFF_CTRL 147456
#define GSMEM (OFF_CTRL + 2560)

// recur smem layout
#define WPITCH 520                    // bf16 per Wih row (1040 B)
#define OFF_WAL  66560
#define OFF_RED  133120
#define OFF_BIAS (OFF_RED + 32768)
#define OFF_CSH  (OFF_BIAS + 256)
#define RSMEM    (OFF_CSH + 1024)     // 167168

// ---------------- device scratch ----------------
__device__ float  g_ix[(size_t)TT * GG * BB];        // layer-0 input proj [t][gate][b]
__device__ float  g_hs[(size_t)TT * BB * HH];        // final h (head reads t=TT-1)
__device__ unsigned int g_flag[2][NCOL][NRG];        // per-layer per-CTA flags
__device__ __nv_bfloat16 g_embh[(size_t)VOCAB * HH];
__device__ __nv_bfloat16 g_embl[(size_t)VOCAB * HH];
__device__ __nv_bfloat16 g_wihh[(size_t)GG * HH];    // layer-0 Wih hi
__device__ __nv_bfloat16 g_wihl[(size_t)GG * HH];    // layer-0 Wih lo
__device__ __nv_bfloat16 g_hsh[1], g_hsl[1];         // dummies (gemm gather-only)
// fragment-native h exchange: [layer][slot0..3][col][word 0..4095][hi,lo]
// word = (f*2+nt)*32 + gid*4 + tig,  f = kfrag (w*8+ksl*2+p), b = nt*8+gid
__device__ uint32_t g_hf[2][4][NCOL][4096][2];

// ---------------- helpers ----------------
__device__ __forceinline__ unsigned int ld_acq(const unsigned int* p) {
    unsigned int v;
    asm volatile("ld.acquire.gpu.u32 %0, [%1];" : "=r"(v) : "l"(p) : "memory");
    return v;
}
__device__ __forceinline__ void red_release(unsigned int* p, unsigned int v) {
    asm volatile("red.release.gpu.global.add.u32 [%0], %1;" :: "l"(p), "r"(v) : "memory");
}
__device__ __forceinline__ float fast_sigmoid(float x) {
    return __fdividef(1.f, 1.f + __expf(-x));
}
__device__ __forceinline__ float fast_tanh(float x) {
    return 2.f * __fdividef(1.f, 1.f + __expf(-2.f * x)) - 1.f;
}
__device__ __forceinline__ uint32_t smem_u32(const void* p) {
    uint32_t a;
    asm("{ .reg .u64 t; cvta.to.shared.u64 t, %1; cvt.u32.u64 %0, t; }" : "=r"(a) : "l"(p));
    return a;
}
__device__ __forceinline__ void cpa16(uint32_t dst, const void* src) {
    asm volatile("cp.async.cg.shared.global [%0], [%1], 16;" :: "r"(dst), "l"(src));
}
__device__ __forceinline__ void cpa_commit() {
    asm volatile("cp.async.commit_group;" ::: "memory");
}
template <int N> __device__ __forceinline__ void cpa_wait() {
    asm volatile("cp.async.wait_group %0;" :: "n"(N) : "memory");
}
__device__ __forceinline__ void ldsm4(uint32_t* r, uint32_t addr) {
    asm volatile("ldmatrix.sync.aligned.m8n8.x4.shared.b16 {%0,%1,%2,%3}, [%4];"
                 : "=r"(r[0]), "=r"(r[1]), "=r"(r[2]), "=r"(r[3]) : "r"(addr));
}
__device__ __forceinline__ void mma16816(float* d, const uint32_t* a, uint32_t b0, uint32_t b1) {
    asm volatile("mma.sync.aligned.m16n8k16.row.col.f32.bf16.bf16.f32 "
                 "{%0,%1,%2,%3}, {%4,%5,%6,%7}, {%8,%9}, {%0,%1,%2,%3};"
                 : "+f"(d[0]), "+f"(d[1]), "+f"(d[2]), "+f"(d[3])
                 : "r"(a[0]), "r"(a[1]), "r"(a[2]), "r"(a[3]), "r"(b0), "r"(b1));
}
__device__ __forceinline__ void split_pack(float2 v, uint32_t& hi, uint32_t& lo) {
    __nv_bfloat16 hx = __float2bfloat16(v.x), hy = __float2bfloat16(v.y);
    __nv_bfloat16 lx = __float2bfloat16(v.x - __bfloat162float(hx));
    __nv_bfloat16 ly = __float2bfloat16(v.y - __bfloat162float(hy));
    hi = ((uint32_t)__bfloat16_as_ushort(hy) << 16) | __bfloat16_as_ushort(hx);
    lo = ((uint32_t)__bfloat16_as_ushort(ly) << 16) | __bfloat16_as_ushort(lx);
}

// ---------------- hi/lo conversion (emb + layer-0 Wih) ----------------
__global__ void cvt_hilo(const float* __restrict__ src, int sel, size_t n)
{
    __nv_bfloat16 *hi, *lo;
    if (sel == 0) { hi = g_embh; lo = g_embl; }
    else          { hi = g_wihh; lo = g_wihl; }
    size_t stride = (size_t)gridDim.x * blockDim.x * 4;
    for (size_t v = ((size_t)blockIdx.x * blockDim.x + threadIdx.x) * 4; v < n; v += stride) {
        float4 f = *(const float4*)(src + v);
        __nv_bfloat16 h0 = __float2bfloat16(f.x), h1 = __float2bfloat16(f.y);
        __nv_bfloat16 h2 = __float2bfloat16(f.z), h3 = __float2bfloat16(f.w);
        __nv_bfloat16 l0 = __float2bfloat16(f.x - __bfloat162float(h0));
        __nv_bfloat16 l1 = __float2bfloat16(f.y - __bfloat162float(h1));
        __nv_bfloat16 l2 = __float2bfloat16(f.z - __bfloat162float(h2));
        __nv_bfloat16 l3 = __float2bfloat16(f.w - __bfloat162float(h3));
        *(__nv_bfloat162*)(hi + v)     = __halves2bfloat162(h0, h1);
        *(__nv_bfloat162*)(hi + v + 2) = __halves2bfloat162(h2, h3);
        *(__nv_bfloat162*)(lo + v)     = __halves2bfloat162(l0, l1);
        *(__nv_bfloat162*)(lo + v + 2) = __halves2bfloat162(l2, l3);
    }
}

// ---------------- warp-MMA input-projection GEMM (layer 0, gather) ----------------
__global__ void __launch_bounds__(256, 1) gemm_mma(
    const int* __restrict__ x, const float* __restrict__ bi,
    const float* __restrict__ bh)
{
    extern __shared__ __align__(128) char smem[];
    const __nv_bfloat16** rp_hi = (const __nv_bfloat16**)(smem + OFF_CTRL);
    const __nv_bfloat16** rp_lo = (const __nv_bfloat16**)(smem + OFF_CTRL + 1024);
    float* biassh = (float*)(smem + OFF_CTRL + 2048);

    int tid = threadIdx.x, wid = tid >> 5, lane = tid & 31;
    int n0 = blockIdx.x * GN, m0 = blockIdx.y * GM;
    uint32_t sb = smem_u32(smem);

    if (tid < 128) {
        int mg = m0 + tid;
        int t = mg >> 5, b = mg & 31;
        size_t rowoff = (size_t)x[b * TT + t] * HH;
        rp_hi[tid] = g_embh + rowoff;
        rp_lo[tid] = g_embl + rowoff;
        biassh[tid] = bi[n0 + tid] + bh[n0 + tid];
    }
    __syncthreads();

    auto load_chunk = [&](int c, int s) {
        uint32_t base = sb + s * STAGE;
        const __nv_bfloat16* w_h = g_wihh + (size_t)n0 * HH + c * KC;
        const __nv_bfloat16* w_l = g_wihl + (size_t)n0 * HH + c * KC;
#pragma unroll
        for (int it = 0; it < 4; ++it) {
            int task = it * 256 + tid;
            int row = task >> 3, q = task & 7;
            uint32_t off = row * RSB + q * 16;
            cpa16(base + OFF_A_HI + off, (const char*)(rp_hi[row] + c * KC) + q * 16);
            cpa16(base + OFF_A_LO + off, (const char*)(rp_lo[row] + c * KC) + q * 16);
            cpa16(base + OFF_B_HI + off, (const char*)(w_h + (size_t)row * HH) + q * 16);
            cpa16(base + OFF_B_LO + off, (const char*)(w_l + (size_t)row * HH) + q * 16);
        }
    };

    int wm = wid >> 1, wn = wid & 1;
    int m0w = wm * 32, n0w = wn * 64;

    float acc[64];
#pragma unroll
    for (int i = 0; i < 64; ++i) acc[i] = 0.f;

    load_chunk(0, 0);
    cpa_commit();

    for (int c = 0; c < 8; ++c) {
        if (c < 7) {
            load_chunk(c + 1, (c + 1) & 1);
            cpa_commit();
            cpa_wait<1>();
        } else {
            cpa_wait<0>();
        }
        __syncthreads();

        uint32_t sbase = sb + (c & 1) * STAGE;
#pragma unroll
        for (int ks = 0; ks < 4; ++ks) {
            uint32_t a_h[2][4], a_l[2][4];
#pragma unroll
            for (int mt = 0; mt < 2; ++mt) {
                uint32_t row = m0w + mt * 16 + (lane & 15);
                uint32_t kb = ks * 32 + (lane >> 4) * 16;
                ldsm4(a_h[mt], sbase + OFF_A_HI + row * RSB + kb);
                ldsm4(a_l[mt], sbase + OFF_A_LO + row * RSB + kb);
            }
            uint32_t b_h[4][4], b_l[4][4];
#pragma unroll
            for (int p = 0; p < 4; ++p) {
                uint32_t row = n0w + p * 16 + ((lane >> 4) << 3) + (lane & 7);
                uint32_t kb = ks * 32 + ((lane >> 3) & 1) * 16;
                ldsm4(b_h[p], sbase + OFF_B_HI + row * RSB + kb);
                ldsm4(b_l[p], sbase + OFF_B_LO + row * RSB + kb);
            }
#pragma unroll
            for (int mt = 0; mt < 2; ++mt)
#pragma unroll
                for (int p = 0; p < 4; ++p)
#pragma unroll
                    for (int h = 0; h < 2; ++h) {
                        float* d = &acc[(mt * 8 + p * 2 + h) * 4];
                        mma16816(d, a_h[mt], b_h[p][2 * h], b_h[p][2 * h + 1]);
                        mma16816(d, a_h[mt], b_l[p][2 * h], b_l[p][2 * h + 1]);
                        mma16816(d, a_l[mt], b_h[p][2 * h], b_h[p][2 * h + 1]);
                    }
        }
        __syncthreads();
    }

    float* Cs = (float*)smem;   // [128][129]
#pragma unroll
    for (int mt = 0; mt < 2; ++mt)
#pragma unroll
        for (int nt = 0; nt < 8; ++nt) {
            const float* d = &acc[(mt * 8 + nt) * 4];
            int r0 = m0w + mt * 16 + (lane >> 2);
            int c0 = n0w + nt * 8 + 2 * (lane & 3);
            Cs[r0 * 129 + c0]           = d[0];
            Cs[r0 * 129 + c0 + 1]       = d[1];
            Cs[(r0 + 8) * 129 + c0]     = d[2];
            Cs[(r0 + 8) * 129 + c0 + 1] = d[3];
        }
    __syncthreads();

#pragma unroll
    for (int it = 0; it < 2; ++it) {
        int task = it * 256 + tid;
        int tl = task >> 7, n = task & 127;
        float bias = biassh[n];
        int t = (m0 >> 5) + tl;
        int ng = n0 + n;
        float* dst = &g_ix[((size_t)t * GG + ng) * BB];
#pragma unroll
        for (int bq = 0; bq < 8; ++bq) {
            float4 v;
            v.x = Cs[(tl * 32 + bq * 4 + 0) * 129 + n] + bias;
            v.y = Cs[(tl * 32 + bq * 4 + 1) * 129 + n] + bias;
            v.z = Cs[(tl * 32 + bq * 4 + 2) * 129 + n] + bias;
            v.w = Cs[(tl * 32 + bq * 4 + 3) * 129 + n] + bias;
            *(float4*)(dst + bq * 4) = v;
        }
    }
}

// ---------------- fused two-layer persistent recurrence ----------------
// 128 CTAs: [0,64) layer 0, [64,128) layer 1. Per CTA: col j, row-group i,
// units [16i,16i+16), batches [16j,16j+16). 8 MMA warps (k slice 64 each) +
// 1 poller warp. Layer 1 also computes Wih1 @ h0[t] (Wih1 slice in SMEM).
__global__ __launch_bounds__(RT, 1) void recur_fused(
    const float* __restrict__ Whh, const float* __restrict__ Wih,
    const float* __restrict__ bih, const float* __restrict__ bhh)
{
    extern __shared__ char smem[];
    __nv_bfloat16* WAh = (__nv_bfloat16*)smem;              // [64][520]
    __nv_bfloat16* WAl = (__nv_bfloat16*)(smem + OFF_WAL);
    float* red    = (float*)(smem + OFF_RED);               // [8][64][16]
    float* biassh = (float*)(smem + OFF_BIAS);              // [64]
    float* csh    = (float*)(smem + OFF_CSH);               // [256]

    int tid = threadIdx.x;
    int lane = tid & 31, w = tid >> 5;
    int gid = lane >> 2, tig = lane & 3;
    int L = blockIdx.x >> 6;          // layer role
    int idx = blockIdx.x & 63;
    int j = idx >> 5, i = idx & 31;
    int U0 = i * NU, B0 = j * BPC;

    const float* WhhL = Whh + (size_t)L * GG * HH;

    // Whh slice frags in registers (all CTAs)
    uint32_t Ah[4][4][4], Al[4][4][4];
    if (w < 8) {
#pragma unroll
        for (int g = 0; g < 4; ++g) {
            const float* r0 = WhhL + (size_t)(g * HH + U0 + gid) * HH;
            const float* r8 = r0 + (size_t)8 * HH;
#pragma unroll
            for (int ksl = 0; ksl < 4; ++ksl) {
                int k = (w * 4 + ksl) * 16 + tig * 2;
                split_pack(*(const float2*)(r0 + k),     Ah[g][ksl][0], Al[g][ksl][0]);
                split_pack(*(const float2*)(r8 + k),     Ah[g][ksl][1], Al[g][ksl][1]);
                split_pack(*(const float2*)(r0 + k + 8), Ah[g][ksl][2], Al[g][ksl][2]);
                split_pack(*(const float2*)(r8 + k + 8), Ah[g][ksl][3], Al[g][ksl][3]);
            }
        }
    }
    // layer 1: Wih1 slice into SMEM + bias
    if (L == 1) {
        for (int v = tid; v < 64 * 512; v += RT) {
            int r = v >> 9, k = v & 511;
            int grow = (r >> 4) * HH + U0 + (r & 15);
            float f = Wih[(size_t)GG * HH + (size_t)grow * HH + k];
            __nv_bfloat16 fh = __float2bfloat16(f);
            WAh[r * WPITCH + k] = fh;
            WAl[r * WPITCH + k] = __float2bfloat16(f - __bfloat162float(fh));
        }
        if (tid < 64) {
            int grow = (tid >> 4) * HH + U0 + (tid & 15);
            biassh[tid] = bih[GG + grow] + bhh[GG + grow];
        }
    }
    if (tid < 256) csh[tid] = 0.f;
    __syncthreads();

    int cu = tid >> 4, cb = tid & 15;                 // cell identity (tid<256)
    unsigned int* myflag = &g_flag[L][j][i];
    uint32_t wa_h = smem_u32(WAh), wa_l = smem_u32(WAl);

    // producer word index
    int pk = U0 + cu;
    int pm = pk >> 1;
    int pf = (pm >> 5) * 8 + ((pm >> 3) & 3) * 2 + ((pm >> 2) & 1);
    int pW = (pf * 2 + (cb >> 3)) * 32 + (cb & 7) * 4 + (pm & 3);
    int phalf = pk & 1;

    for (int t = 0; t < TT; ++t) {
        float ixv[4];
        if (tid < 256) {
            if (L == 0) {
#pragma unroll
                for (int g = 0; g < 4; ++g)
                    ixv[g] = g_ix[((size_t)t * GG + g * HH + U0 + cu) * BB + B0 + cb];
            }
        } else {
            // poller warp: lane l watches CTA l of this column
            int l = tid - 256;
            const unsigned int* fOwn = &g_flag[L][j][l];
            unsigned int aOwn = 256u * (unsigned)(t + 1);
            if (L == 1) {
                const unsigned int* f0 = &g_flag[0][j][l];
                unsigned int a0 = 256u * (unsigned)(t + 2);
                while (!__all_sync(0xFFFFFFFFu,
                        ld_acq(fOwn) >= aOwn && ld_acq(f0) >= a0)) {}
            } else if (t >= 3) {
                const unsigned int* f1 = &g_flag[1][j][l];
                unsigned int a1 = 256u * (unsigned)(t - 2);   // back-pressure (depth-4 h0 buf)
                while (!__all_sync(0xFFFFFFFFu,
                        ld_acq(fOwn) >= aOwn && ld_acq(f1) >= a1)) {}
            } else {
                while (!__all_sync(0xFFFFFFFFu, ld_acq(fOwn) >= aOwn)) {}
            }
        }
        __syncthreads();

        if (w < 8) {
            const uint2* hfO = (const uint2*)&g_hf[L][t & 3][j][0][0];
            const uint2* hf0 = (const uint2*)&g_hf[0][(t + 1) & 3][j][0][0];

            float d[4][2][4];
#pragma unroll
            for (int g = 0; g < 4; ++g)
#pragma unroll
                for (int nt = 0; nt < 2; ++nt)
#pragma unroll
                    for (int q = 0; q < 4; ++q) d[g][nt][q] = 0.f;

#pragma unroll
            for (int ksl = 0; ksl < 4; ++ksl) {
                int i0 = (w * 8 + ksl * 2) * 64 + lane;
                uint2 ob0[2], ob1[2];
                ob0[0] = hfO[i0];       ob0[1] = hfO[i0 + 32];
                ob1[0] = hfO[i0 + 64];  ob1[1] = hfO[i0 + 96];
#pragma unroll
                for (int g = 0; g < 4; ++g)
#pragma unroll
                    for (int nt = 0; nt < 2; ++nt) {
                        mma16816(d[g][nt], Ah[g][ksl], ob0[nt].x, ob1[nt].x);
                        mma16816(d[g][nt], Ah[g][ksl], ob0[nt].y, ob1[nt].y);
                        mma16816(d[g][nt], Al[g][ksl], ob0[nt].x, ob1[nt].x);
                    }
                if (L == 1) {
                    uint2 zb0[2], zb1[2];
                    zb0[0] = hf0[i0];       zb0[1] = hf0[i0 + 32];
                    zb1[0] = hf0[i0 + 64];  zb1[1] = hf0[i0 + 96];
                    uint32_t koff = (w * 4 + ksl) * 32 + (lane >> 4) * 16;
                    uint32_t rbase = (lane & 15) * (WPITCH * 2);
#pragma unroll
                    for (int g = 0; g < 4; ++g) {
                        uint32_t ah[4], al[4];
                        ldsm4(ah, wa_h + (g * 16) * (WPITCH * 2) + rbase + koff);
                        ldsm4(al, wa_l + (g * 16) * (WPITCH * 2) + rbase + koff);
#pragma unroll
                        for (int nt = 0; nt < 2; ++nt) {
                            mma16816(d[g][nt], ah, zb0[nt].x, zb1[nt].x);
                            mma16816(d[g][nt], ah, zb0[nt].y, zb1[nt].y);
                            mma16816(d[g][nt], al, zb0[nt].x, zb1[nt].x);
                        }
                    }
                }
            }
            // partials -> red: float2, conflict-spread addresses
            float2* r64 = (float2*)red;
            int base = w * 512;
#pragma unroll
            for (int g = 0; g < 4; ++g)
#pragma unroll
                for (int nt = 0; nt < 2; ++nt) {
                    r64[base + (g * 16 + gid) * 8 + nt * 4 + tig] =
                        make_float2(d[g][nt][0], d[g][nt][1]);
                    r64[base + (g * 16 + 8 + gid) * 8 + nt * 4 + tig] =
                        make_float2(d[g][nt][2], d[g][nt][3]);
                }
        }
        __syncthreads();

        if (tid < 256) {
            float gate[4];
#pragma unroll
            for (int g = 0; g < 4; ++g) {
                float s = (L == 1) ? biassh[g * 16 + cu] : ixv[g];
                int ro = (g * 16 + cu) * 16 + cb;
#pragma unroll
                for (int ww = 0; ww < 8; ++ww)
                    s += red[ww * 1024 + ro];
                gate[g] = s;
            }
            float si = fast_sigmoid(gate[0]);
            float sf = fast_sigmoid(gate[1]);
            float gg = fast_tanh(gate[2]);
            float so = fast_sigmoid(gate[3]);
            float c  = sf * csh[tid] + si * gg;
            float h  = so * fast_tanh(c);

            __nv_bfloat16 hh = __float2bfloat16(h);
            __nv_bfloat16 hl = __float2bfloat16(h - __bfloat162float(hh));
            __nv_bfloat16* dst = (__nv_bfloat16*)&g_hf[L][(t + 1) & 3][j][0][0];
            dst[pW * 4 + phalf]     = hh;
            dst[pW * 4 + 2 + phalf] = hl;
            red_release(myflag, 1u);

            csh[tid] = c;
            if (L == 1 && t == TT - 1)
                g_hs[((size_t)t * BB + B0 + cb) * HH + pk] = h;
        }
    }
}

// ---------------- head ----------------
__global__ void head_kernel(const float* __restrict__ fcw, const float* __restrict__ fcb,
                            const int* __restrict__ labels, float* __restrict__ out, int out_size)
{
    __shared__ float lg[128];
    __shared__ float pl[32];
    int tid = threadIdx.x;
    int b = tid >> 2, c = tid & 3;
    const float* h = g_hs + ((size_t)(TT - 1) * BB + b) * HH;
    const float* wr = fcw + c * HH;
    float acc = 0.f;
#pragma unroll 8
    for (int k = 0; k < HH; k += 4) {
        float4 hv = *(const float4*)(h + k);
        float4 wv = *(const float4*)(wr + k);
        acc += hv.x * wv.x + hv.y * wv.y + hv.z * wv.z + hv.w * wv.w;
    }
    lg[b * 4 + c] = acc + fcb[c];
    __syncthreads();
    if (tid < 32) {
        float l0 = lg[tid * 4], l1 = lg[tid * 4 + 1], l2 = lg[tid * 4 + 2], l3 = lg[tid * 4 + 3];
        float m = fmaxf(fmaxf(l0, l1), fmaxf(l2, l3));
        float lse = m + logf(expf(l0 - m) + expf(l1 - m) + expf(l2 - m) + expf(l3 - m));
        int lab = labels[tid];
        pl[tid] = lg[tid * 4 + lab] - lse;
    }
    __syncthreads();
    if (tid == 0) {
        float s = 0.f;
        for (int i = 0; i < 32; i++) s += pl[i];
        float loss = -s / 32.f;
        if (out_size == 128) {
            for (int i = 0; i < 128; i++) out[i] = lg[i];
        } else {
            out[0] = loss;
            int n = out_size - 1; if (n > 128) n = 128;
            for (int i = 0; i < n; i++) out[1 + i] = lg[i];
            for (int i = 129; i < out_size; i++) out[i] = 0.f;
        }
    }
}

__global__ void init_kernel() {
    int idx = blockIdx.x * blockDim.x + threadIdx.x;
    int total = 2 * 4 * NCOL * 4096 * 2;   // uint32 words in g_hf
    uint32_t* ph = (uint32_t*)&g_hf[0][0][0][0][0];
    for (int v = idx; v < total; v += gridDim.x * blockDim.x)
        ph[v] = 0u;
    if (idx < 2 * NCOL * NRG)
        ((unsigned int*)&g_flag[0][0][0])[idx] = 256u;
}

// ---------------- launch ----------------
extern "C" void kernel_launch(void* const* d_in, const int* in_sizes, int n_in,
                              void* d_out, int out_size)
{
    const int*   x      = (const int*)d_in[0];
    const int*   labels = (const int*)d_in[1];
    const float* emb    = (const float*)d_in[2];
    const float* Wih    = (const float*)d_in[3];
    const float* Whh    = (const float*)d_in[4];
    const float* bih    = (const float*)d_in[5];
    const float* bhh    = (const float*)d_in[6];
    const float* fcw    = (const float*)d_in[7];
    const float* fcb    = (const float*)d_in[8];
    float* out = (float*)d_out;

    cudaFuncSetAttribute(gemm_mma, cudaFuncAttributeMaxDynamicSharedMemorySize, GSMEM);
    cudaFuncSetAttribute(recur_fused, cudaFuncAttributeMaxDynamicSharedMemorySize, RSMEM);

    init_kernel<<<64, 256>>>();
    cvt_hilo<<<1024, 256>>>(emb, 0, (size_t)VOCAB * HH);
    cvt_hilo<<<256, 256>>>(Wih, 1, (size_t)GG * HH);

    dim3 gg(GG / GN, (TT * BB) / GM);   // (16, 512)
    gemm_mma<<<gg, 256, GSMEM>>>(x, bih, bhh);
    recur_fused<<<128, RT, RSMEM>>>(Whh, Wih, bih, bhh);
    head_kernel<<<1, 128>>>(fcw, fcb, labels, out, out_size);
}

// round 15
// speedup vs baseline: 1.3155x; 1.3155x over previous
#include <cuda_runtime.h>
#include <cuda_bf16.h>
#include <cstdint>

#define TT 2048
#define BB 32
#define HH 512
#define GG 2048            // 4*H
#define VOCAB 32000
#define NCOL 4             // batch columns
#define BPC 8              // batches per column
#define NRG 32             // row-groups (CTAs per column)
#define NU 16              // hidden units per CTA
#define RT 256             // recurrence threads (8 warps)

// GEMM geometry
#define GM 128
#define GN 128
#define KC 64
#define RSB 144
#define STAGE 73728
#define OFF_A_HI 0
#define OFF_A_LO 18432
#define OFF_B_HI 36864
#define OFF_B_LO 55296
#define OFF_CTRL 147456
#define GSMEM (OFF_CTRL + 2560)

// ---------------- device scratch ----------------
__device__ float  g_ix[(size_t)TT * GG * BB];        // [t][gate_row][b]
__device__ float  g_hs[(size_t)TT * BB * HH];        // only last-step f32 h (head)
__device__ unsigned int g_flag[2][NCOL][NRG];        // per-CTA progress flags
__device__ __nv_bfloat16 g_embh[(size_t)VOCAB * HH];
__device__ __nv_bfloat16 g_embl[(size_t)VOCAB * HH];
__device__ __nv_bfloat16 g_wihh[(size_t)2 * GG * HH];
__device__ __nv_bfloat16 g_wihl[(size_t)2 * GG * HH];
__device__ __nv_bfloat16 g_hsh[(size_t)TT * BB * HH];   // layer-0 h hi  [t][b][k]
__device__ __nv_bfloat16 g_hsl[(size_t)TT * BB * HH];   // layer-0 h lo
// fragment-native h exchange: [layer][par][col][word 0..2047][0]=hi,[1]=lo (uint32 bf16x2)
__device__ uint32_t g_hf[2][2][NCOL][2048][2];

// ---------------- helpers ----------------
__device__ __forceinline__ unsigned int ld_acq(const unsigned int* p) {
    unsigned int v;
    asm volatile("ld.acquire.gpu.u32 %0, [%1];" : "=r"(v) : "l"(p) : "memory");
    return v;
}
__device__ __forceinline__ void red_release(unsigned int* p, unsigned int v) {
    asm volatile("red.release.gpu.global.add.u32 [%0], %1;" :: "l"(p), "r"(v) : "memory");
}
__device__ __forceinline__ float fast_sigmoid(float x) {
    return __fdividef(1.f, 1.f + __expf(-x));
}
__device__ __forceinline__ float fast_tanh(float x) {
    return 2.f * __fdividef(1.f, 1.f + __expf(-2.f * x)) - 1.f;
}
__device__ __forceinline__ uint32_t smem_u32(const void* p) {
    uint32_t a;
    asm("{ .reg .u64 t; cvta.to.shared.u64 t, %1; cvt.u32.u64 %0, t; }" : "=r"(a) : "l"(p));
    return a;
}
__device__ __forceinline__ void cpa16(uint32_t dst, const void* src) {
    asm volatile("cp.async.cg.shared.global [%0], [%1], 16;" :: "r"(dst), "l"(src));
}
__device__ __forceinline__ void cpa_commit() {
    asm volatile("cp.async.commit_group;" ::: "memory");
}
template <int N> __device__ __forceinline__ void cpa_wait() {
    asm volatile("cp.async.wait_group %0;" :: "n"(N) : "memory");
}
__device__ __forceinline__ void ldsm4(uint32_t* r, uint32_t addr) {
    asm volatile("ldmatrix.sync.aligned.m8n8.x4.shared.b16 {%0,%1,%2,%3}, [%4];"
                 : "=r"(r[0]), "=r"(r[1]), "=r"(r[2]), "=r"(r[3]) : "r"(addr));
}
__device__ __forceinline__ void mma16816(float* d, const uint32_t* a, uint32_t b0, uint32_t b1) {
    asm volatile("mma.sync.aligned.m16n8k16.row.col.f32.bf16.bf16.f32 "
                 "{%0,%1,%2,%3}, {%4,%5,%6,%7}, {%8,%9}, {%0,%1,%2,%3};"
                 : "+f"(d[0]), "+f"(d[1]), "+f"(d[2]), "+f"(d[3])
                 : "r"(a[0]), "r"(a[1]), "r"(a[2]), "r"(a[3]), "r"(b0), "r"(b1));
}
__device__ __forceinline__ void split_pack(float2 v, uint32_t& hi, uint32_t& lo) {
    __nv_bfloat16 hx = __float2bfloat16(v.x), hy = __float2bfloat16(v.y);
    __nv_bfloat16 lx = __float2bfloat16(v.x - __bfloat162float(hx));
    __nv_bfloat16 ly = __float2bfloat16(v.y - __bfloat162float(hy));
    hi = ((uint32_t)__bfloat16_as_ushort(hy) << 16) | __bfloat16_as_ushort(hx);
    lo = ((uint32_t)__bfloat16_as_ushort(ly) << 16) | __bfloat16_as_ushort(lx);
}

// ---------------- hi/lo conversion (emb, Wih only) ----------------
__global__ void cvt_hilo(const float* __restrict__ src, int sel, size_t n)
{
    __nv_bfloat16 *hi, *lo;
    if (sel == 0) { hi = g_embh; lo = g_embl; }
    else          { hi = g_wihh; lo = g_wihl; }
    size_t stride = (size_t)gridDim.x * blockDim.x * 4;
    for (size_t v = ((size_t)blockIdx.x * blockDim.x + threadIdx.x) * 4; v < n; v += stride) {
        float4 f = *(const float4*)(src + v);
        __nv_bfloat16 h0 = __float2bfloat16(f.x), h1 = __float2bfloat16(f.y);
        __nv_bfloat16 h2 = __float2bfloat16(f.z), h3 = __float2bfloat16(f.w);
        __nv_bfloat16 l0 = __float2bfloat16(f.x - __bfloat162float(h0));
        __nv_bfloat16 l1 = __float2bfloat16(f.y - __bfloat162float(h1));
        __nv_bfloat16 l2 = __float2bfloat16(f.z - __bfloat162float(h2));
        __nv_bfloat16 l3 = __float2bfloat16(f.w - __bfloat162float(h3));
        *(__nv_bfloat162*)(hi + v)     = __halves2bfloat162(h0, h1);
        *(__nv_bfloat162*)(hi + v + 2) = __halves2bfloat162(h2, h3);
        *(__nv_bfloat162*)(lo + v)     = __halves2bfloat162(l0, l1);
        *(__nv_bfloat162*)(lo + v + 2) = __halves2bfloat162(l2, l3);
    }
}

// ---------------- warp-MMA input-projection GEMM (bf16x3, unchanged) ----------------
__global__ void __launch_bounds__(256, 1) gemm_mma(
    const int* __restrict__ x, const float* __restrict__ bi,
    const float* __restrict__ bh, int use_gather, int layer)
{
    extern __shared__ __align__(128) char smem[];
    const __nv_bfloat16** rp_hi = (const __nv_bfloat16**)(smem + OFF_CTRL);
    const __nv_bfloat16** rp_lo = (const __nv_bfloat16**)(smem + OFF_CTRL + 1024);
    float* biassh = (float*)(smem + OFF_CTRL + 2048);

    int tid = threadIdx.x, wid = tid >> 5, lane = tid & 31;
    int n0 = blockIdx.x * GN, m0 = blockIdx.y * GM;
    uint32_t sb = smem_u32(smem);

    const __nv_bfloat16* ah = use_gather ? g_embh : g_hsh;
    const __nv_bfloat16* al = use_gather ? g_embl : g_hsl;
    const __nv_bfloat16* whi = g_wihh + (size_t)layer * GG * HH;
    const __nv_bfloat16* wlo = g_wihl + (size_t)layer * GG * HH;

    if (tid < 128) {
        int mg = m0 + tid;
        size_t rowoff;
        if (use_gather) {
            int t = mg >> 5, b = mg & 31;
            rowoff = (size_t)x[b * TT + t] * HH;
        } else {
            rowoff = (size_t)mg * HH;
        }
        rp_hi[tid] = ah + rowoff;
        rp_lo[tid] = al + rowoff;
        biassh[tid] = bi[n0 + tid] + bh[n0 + tid];
    }
    __syncthreads();

    auto load_chunk = [&](int c, int s) {
        uint32_t base = sb + s * STAGE;
        const __nv_bfloat16* w_h = whi + (size_t)n0 * HH + c * KC;
        const __nv_bfloat16* w_l = wlo + (size_t)n0 * HH + c * KC;
#pragma unroll
        for (int it = 0; it < 4; ++it) {
            int task = it * 256 + tid;
            int row = task >> 3, q = task & 7;
            uint32_t off = row * RSB + q * 16;
            cpa16(base + OFF_A_HI + off, (const char*)(rp_hi[row] + c * KC) + q * 16);
            cpa16(base + OFF_A_LO + off, (const char*)(rp_lo[row] + c * KC) + q * 16);
            cpa16(base + OFF_B_HI + off, (const char*)(w_h + (size_t)row * HH) + q * 16);
            cpa16(base + OFF_B_LO + off, (const char*)(w_l + (size_t)row * HH) + q * 16);
        }
    };

    int wm = wid >> 1, wn = wid & 1;
    int m0w = wm * 32, n0w = wn * 64;

    float acc[64];
#pragma unroll
    for (int i = 0; i < 64; ++i) acc[i] = 0.f;

    load_chunk(0, 0);
    cpa_commit();

    for (int c = 0; c < 8; ++c) {
        if (c < 7) {
            load_chunk(c + 1, (c + 1) & 1);
            cpa_commit();
            cpa_wait<1>();
        } else {
            cpa_wait<0>();
        }
        __syncthreads();

        uint32_t sbase = sb + (c & 1) * STAGE;
#pragma unroll
        for (int ks = 0; ks < 4; ++ks) {
            uint32_t a_h[2][4], a_l[2][4];
#pragma unroll
            for (int mt = 0; mt < 2; ++mt) {
                uint32_t row = m0w + mt * 16 + (lane & 15);
                uint32_t kb = ks * 32 + (lane >> 4) * 16;
                ldsm4(a_h[mt], sbase + OFF_A_HI + row * RSB + kb);
                ldsm4(a_l[mt], sbase + OFF_A_LO + row * RSB + kb);
            }
            uint32_t b_h[4][4], b_l[4][4];
#pragma unroll
            for (int p = 0; p < 4; ++p) {
                uint32_t row = n0w + p * 16 + ((lane >> 4) << 3) + (lane & 7);
                uint32_t kb = ks * 32 + ((lane >> 3) & 1) * 16;
                ldsm4(b_h[p], sbase + OFF_B_HI + row * RSB + kb);
                ldsm4(b_l[p], sbase + OFF_B_LO + row * RSB + kb);
            }
#pragma unroll
            for (int mt = 0; mt < 2; ++mt)
#pragma unroll
                for (int p = 0; p < 4; ++p)
#pragma unroll
                    for (int h = 0; h < 2; ++h) {
                        float* d = &acc[(mt * 8 + p * 2 + h) * 4];
                        mma16816(d, a_h[mt], b_h[p][2 * h], b_h[p][2 * h + 1]);
                        mma16816(d, a_h[mt], b_l[p][2 * h], b_l[p][2 * h + 1]);
                        mma16816(d, a_l[mt], b_h[p][2 * h], b_h[p][2 * h + 1]);
                    }
        }
        __syncthreads();
    }

    float* Cs = (float*)smem;   // [128][129]
#pragma unroll
    for (int mt = 0; mt < 2; ++mt)
#pragma unroll
        for (int nt = 0; nt < 8; ++nt) {
            const float* d = &acc[(mt * 8 + nt) * 4];
            int r0 = m0w + mt * 16 + (lane >> 2);
            int c0 = n0w + nt * 8 + 2 * (lane & 3);
            Cs[r0 * 129 + c0]           = d[0];
            Cs[r0 * 129 + c0 + 1]       = d[1];
            Cs[(r0 + 8) * 129 + c0]     = d[2];
            Cs[(r0 + 8) * 129 + c0 + 1] = d[3];
        }
    __syncthreads();

#pragma unroll
    for (int it = 0; it < 2; ++it) {
        int task = it * 256 + tid;
        int tl = task >> 7, n = task & 127;
        float bias = biassh[n];
        int t = (m0 >> 5) + tl;
        int ng = n0 + n;
        float* dst = &g_ix[((size_t)t * GG + ng) * BB];
#pragma unroll
        for (int bq = 0; bq < 8; ++bq) {
            float4 v;
            v.x = Cs[(tl * 32 + bq * 4 + 0) * 129 + n] + bias;
            v.y = Cs[(tl * 32 + bq * 4 + 1) * 129 + n] + bias;
            v.z = Cs[(tl * 32 + bq * 4 + 2) * 129 + n] + bias;
            v.w = Cs[(tl * 32 + bq * 4 + 3) * 129 + n] + bias;
            *(float4*)(dst + bq * 4) = v;
        }
    }
}

// ---------------- tensor-core persistent recurrence ----------------
// R11 core + (a) hoisted B loads (MLP=8), (b) split accumulators (chain 12->8).
__global__ __launch_bounds__(RT, 1) void recur_mma(const float* __restrict__ Whh, int layer)
{
    __shared__ float red[8 * 64 * 8];   // [w][row64][b8] 16KB
    __shared__ float csh[128];

    int tid = threadIdx.x;
    int lane = tid & 31, w = tid >> 5;
    int gid = lane >> 2, tig = lane & 3;
    int j = blockIdx.x >> 5;          // column
    int i = blockIdx.x & 31;          // row-group
    int U0 = i * NU, B0 = j * BPC;

    // ---- prologue: load Whh A-fragments (bf16 hi/lo) into registers ----
    uint32_t Ah[4][4][4], Al[4][4][4];
#pragma unroll
    for (int g = 0; g < 4; ++g) {
        const float* r0 = Whh + (size_t)(g * HH + U0 + gid) * HH;
        const float* r8 = r0 + (size_t)8 * HH;
#pragma unroll
        for (int ksl = 0; ksl < 4; ++ksl) {
            int k = (w * 4 + ksl) * 16 + tig * 2;
            split_pack(*(const float2*)(r0 + k),     Ah[g][ksl][0], Al[g][ksl][0]);
            split_pack(*(const float2*)(r8 + k),     Ah[g][ksl][1], Al[g][ksl][1]);
            split_pack(*(const float2*)(r0 + k + 8), Ah[g][ksl][2], Al[g][ksl][2]);
            split_pack(*(const float2*)(r8 + k + 8), Ah[g][ksl][3], Al[g][ksl][3]);
        }
    }
    if (tid < 128) csh[tid] = 0.f;
    __syncthreads();

    int cu = tid >> 3, cb = tid & 7;                    // cell identity (tid<128)
    unsigned int* myflag = &g_flag[layer][j][i];
    int bw = w * 256 + lane;                            // fragment base (uint2 units)

    // producer word index: k = U0+cu -> m = k>>1
    int pk = U0 + cu;
    int pm = pk >> 1;
    int pW = (((pm >> 5) * 8) + (((pm >> 3) & 3) * 2) + ((pm >> 2) & 1)) * 32 + cb * 4 + (pm & 3);
    int phalf = pk & 1;

    for (int t = 0; t < TT; ++t) {
        float ixv[4];
        if (tid < 128) {
#pragma unroll
            for (int g = 0; g < 4; ++g)
                ixv[g] = g_ix[((size_t)t * GG + g * HH + U0 + cu) * BB + B0 + cb];
        } else if (tid < 160) {
            // poller warp: lane l watches flag of CTA l
            const unsigned int* fl = &g_flag[layer][j][tid - 128];
            unsigned int target = 128u * (unsigned)(t + 1);
            while (ld_acq(fl) < target) {}
        }
        __syncthreads();

        int par = t & 1;
        const uint2* hfp = (const uint2*)&g_hf[layer][par][j][0][0];

        // hoist all 8 B-fragment loads (MLP=8 on the L2 round trip)
        uint2 v0[4], v1[4];
#pragma unroll
        for (int ksl = 0; ksl < 4; ++ksl) {
            v0[ksl] = hfp[bw + ksl * 64];
            v1[ksl] = hfp[bw + ksl * 64 + 32];
        }

        // split accumulator sets: dH (Ah*bh + Ah*bl, depth 8), dL (Al*bh, depth 4)
        float dH[4][4], dL[4][4];
#pragma unroll
        for (int g = 0; g < 4; ++g)
#pragma unroll
            for (int q = 0; q < 4; ++q) { dH[g][q] = 0.f; dL[g][q] = 0.f; }

#pragma unroll
        for (int ksl = 0; ksl < 4; ++ksl) {
            uint32_t b0h = v0[ksl].x, b0l = v0[ksl].y;
            uint32_t b1h = v1[ksl].x, b1l = v1[ksl].y;
            mma16816(dH[0], Ah[0][ksl], b0h, b1h);
            mma16816(dH[1], Ah[1][ksl], b0h, b1h);
            mma16816(dH[2], Ah[2][ksl], b0h, b1h);
            mma16816(dH[3], Ah[3][ksl], b0h, b1h);
            mma16816(dL[0], Al[0][ksl], b0h, b1h);
            mma16816(dL[1], Al[1][ksl], b0h, b1h);
            mma16816(dL[2], Al[2][ksl], b0h, b1h);
            mma16816(dL[3], Al[3][ksl], b0h, b1h);
            mma16816(dH[0], Ah[0][ksl], b0l, b1l);
            mma16816(dH[1], Ah[1][ksl], b0l, b1l);
            mma16816(dH[2], Ah[2][ksl], b0l, b1l);
            mma16816(dH[3], Ah[3][ksl], b0l, b1l);
        }
        // partials: red[w][g*16+gid(+8)][2tig..2tig+1] — STS.64, linear in lane
        {
            float2* r64 = (float2*)red;
            int base = w * 256;
#pragma unroll
            for (int g = 0; g < 4; ++g) {
                r64[base + g * 64 + lane]      = make_float2(dH[g][0] + dL[g][0], dH[g][1] + dL[g][1]);
                r64[base + g * 64 + 32 + lane] = make_float2(dH[g][2] + dL[g][2], dH[g][3] + dL[g][3]);
            }
        }
        __syncthreads();

        if (tid < 128) {
            float gate[4];
#pragma unroll
            for (int g = 0; g < 4; ++g) {
                float s = ixv[g];
                int ro = (g * 16 + cu) * 8 + cb;
#pragma unroll
                for (int ww = 0; ww < 8; ++ww)
                    s += red[ww * 512 + ro];
                gate[g] = s;
            }
            float si = fast_sigmoid(gate[0]);
            float sf = fast_sigmoid(gate[1]);
            float gg = fast_tanh(gate[2]);
            float so = fast_sigmoid(gate[3]);
            float c  = sf * csh[tid] + si * gg;
            float h  = so * fast_tanh(c);

            // publish h first (inter-CTA critical path), bookkeeping after
            __nv_bfloat16 hh = __float2bfloat16(h);
            __nv_bfloat16 hl = __float2bfloat16(h - __bfloat162float(hh));
            __nv_bfloat16* dst = (__nv_bfloat16*)&g_hf[layer][(t + 1) & 1][j][0][0];
            dst[pW * 4 + phalf]     = hh;   // hi component
            dst[pW * 4 + 2 + phalf] = hl;   // lo component
            red_release(myflag, 1u);

            csh[tid] = c;
            int bg = B0 + cb;
            if (layer == 0) {
                g_hsh[((size_t)t * BB + bg) * HH + pk] = hh;
                g_hsl[((size_t)t * BB + bg) * HH + pk] = hl;
            } else if (t == TT - 1) {
                g_hs[((size_t)t * BB + bg) * HH + pk] = h;
            }
        }
    }
}

// ---------------- head ----------------
__global__ void head_kernel(const float* __restrict__ fcw, const float* __restrict__ fcb,
                            const int* __restrict__ labels, float* __restrict__ out, int out_size)
{
    __shared__ float lg[128];
    __shared__ float pl[32];
    int tid = threadIdx.x;
    int b = tid >> 2, c = tid & 3;
    const float* h = g_hs + ((size_t)(TT - 1) * BB + b) * HH;
    const float* wr = fcw + c * HH;
    float acc = 0.f;
#pragma unroll 8
    for (int k = 0; k < HH; k += 4) {
        float4 hv = *(const float4*)(h + k);
        float4 wv = *(const float4*)(wr + k);
        acc += hv.x * wv.x + hv.y * wv.y + hv.z * wv.z + hv.w * wv.w;
    }
    lg[b * 4 + c] = acc + fcb[c];
    __syncthreads();
    if (tid < 32) {
        float l0 = lg[tid * 4], l1 = lg[tid * 4 + 1], l2 = lg[tid * 4 + 2], l3 = lg[tid * 4 + 3];
        float m = fmaxf(fmaxf(l0, l1), fmaxf(l2, l3));
        float lse = m + logf(expf(l0 - m) + expf(l1 - m) + expf(l2 - m) + expf(l3 - m));
        int lab = labels[tid];
        pl[tid] = lg[tid * 4 + lab] - lse;
    }
    __syncthreads();
    if (tid == 0) {
        float s = 0.f;
        for (int i = 0; i < 32; i++) s += pl[i];
        float loss = -s / 32.f;
        if (out_size == 128) {
            for (int i = 0; i < 128; i++) out[i] = lg[i];
        } else {
            out[0] = loss;
            int n = out_size - 1; if (n > 128) n = 128;
            for (int i = 0; i < n; i++) out[1 + i] = lg[i];
            for (int i = 129; i < out_size; i++) out[i] = 0.f;
        }
    }
}

__global__ void init_kernel() {
    int idx = blockIdx.x * blockDim.x + threadIdx.x;
    int total = 2 * 2 * NCOL * 2048 * 2;   // uint32 words in g_hf
    uint32_t* ph = (uint32_t*)&g_hf[0][0][0][0][0];
    for (int v = idx; v < total; v += gridDim.x * blockDim.x)
        ph[v] = 0u;
    if (idx < 2 * NCOL * NRG)
        ((unsigned int*)&g_flag[0][0][0])[idx] = 128u;
}

// ---------------- launch ----------------
extern "C" void kernel_launch(void* const* d_in, const int* in_sizes, int n_in,
                              void* d_out, int out_size)
{
    const int*   x      = (const int*)d_in[0];
    const int*   labels = (const int*)d_in[1];
    const float* emb    = (const float*)d_in[2];
    const float* Wih    = (const float*)d_in[3];
    const float* Whh    = (const float*)d_in[4];
    const float* bih    = (const float*)d_in[5];
    const float* bhh    = (const float*)d_in[6];
    const float* fcw    = (const float*)d_in[7];
    const float* fcb    = (const float*)d_in[8];
    float* out = (float*)d_out;

    cudaFuncSetAttribute(gemm_mma, cudaFuncAttributeMaxDynamicSharedMemorySize, GSMEM);

    init_kernel<<<64, 256>>>();
    cvt_hilo<<<1024, 256>>>(emb, 0, (size_t)VOCAB * HH);
    cvt_hilo<<<256, 256>>>(Wih, 1, (size_t)2 * GG * HH);

    dim3 gg(GG / GN, (TT * BB) / GM);   // (16, 512)
    // layer 0
    gemm_mma<<<gg, 256, GSMEM>>>(x, bih, bhh, 1, 0);
    recur_mma<<<NCOL * NRG, RT>>>(Whh, 0);
    // layer 1
    gemm_mma<<<gg, 256, GSMEM>>>(x, bih + GG, bhh + GG, 0, 1);
    recur_mma<<<NCOL * NRG, RT>>>(Whh + (size_t)GG * HH, 1);
    head_kernel<<<1, 128>>>(fcw, fcb, labels, out, out_size);
}

// round 16
// speedup vs baseline: 1.6879x; 1.2830x over previous
#include <cuda_runtime.h>
#include <cuda_bf16.h>
#include <cstdint>

#define TT 2048
#define BB 32
#define HH 512
#define GG 2048            // 4*H
#define VOCAB 32000
#define NCOL 4             // batch columns
#define BPC 8              // batches per column
#define NRG 32             // row-groups (CTAs per column)
#define NU 16              // hidden units per CTA
#define RT 256             // recurrence threads (8 warps)

// GEMM geometry
#define GM 128
#define GN 128
#define KC 64
#define RSB 144
#define STAGE 73728
#define OFF_A_HI 0
#define OFF_A_LO 18432
#define OFF_B_HI 36864
#define OFF_B_LO 55296
#define OFF_CTRL 147456
#define GSMEM (OFF_CTRL + 2560)

// ---------------- device scratch ----------------
__device__ float  g_ix[(size_t)TT * GG * BB];        // [t][gate_row][b]
__device__ float  g_hs[(size_t)TT * BB * HH];        // only last-step f32 h (head)
__device__ __nv_bfloat16 g_embh[(size_t)VOCAB * HH];
__device__ __nv_bfloat16 g_embl[(size_t)VOCAB * HH];
__device__ __nv_bfloat16 g_wihh[(size_t)2 * GG * HH];
__device__ __nv_bfloat16 g_wihl[(size_t)2 * GG * HH];
__device__ __nv_bfloat16 g_hsh[(size_t)TT * BB * HH];   // layer-0 h hi  [t][b][k]
__device__ __nv_bfloat16 g_hsl[(size_t)TT * BB * HH];   // layer-0 h lo
// epoch-stamped fragment-native h exchange:
// g_hf4[layer][par][col][word] = (hi_bf16x2, epoch, lo_bf16x2, epoch)
__device__ uint4 g_hf4[2][2][NCOL][2048];

// ---------------- helpers ----------------
__device__ __forceinline__ uint4 ldv4(const uint4* p) {
    uint4 v;
    asm volatile("ld.volatile.global.v4.u32 {%0,%1,%2,%3}, [%4];"
                 : "=r"(v.x), "=r"(v.y), "=r"(v.z), "=r"(v.w) : "l"(p) : "memory");
    return v;
}
__device__ __forceinline__ void stv4(uint4* p, uint4 v) {
    asm volatile("st.volatile.global.v4.u32 [%0], {%1,%2,%3,%4};"
                 :: "l"(p), "r"(v.x), "r"(v.y), "r"(v.z), "r"(v.w) : "memory");
}
__device__ __forceinline__ float fast_sigmoid(float x) {
    return __fdividef(1.f, 1.f + __expf(-x));
}
__device__ __forceinline__ float fast_tanh(float x) {
    return 2.f * __fdividef(1.f, 1.f + __expf(-2.f * x)) - 1.f;
}
__device__ __forceinline__ uint32_t smem_u32(const void* p) {
    uint32_t a;
    asm("{ .reg .u64 t; cvta.to.shared.u64 t, %1; cvt.u32.u64 %0, t; }" : "=r"(a) : "l"(p));
    return a;
}
__device__ __forceinline__ void cpa16(uint32_t dst, const void* src) {
    asm volatile("cp.async.cg.shared.global [%0], [%1], 16;" :: "r"(dst), "l"(src));
}
__device__ __forceinline__ void cpa_commit() {
    asm volatile("cp.async.commit_group;" ::: "memory");
}
template <int N> __device__ __forceinline__ void cpa_wait() {
    asm volatile("cp.async.wait_group %0;" :: "n"(N) : "memory");
}
__device__ __forceinline__ void ldsm4(uint32_t* r, uint32_t addr) {
    asm volatile("ldmatrix.sync.aligned.m8n8.x4.shared.b16 {%0,%1,%2,%3}, [%4];"
                 : "=r"(r[0]), "=r"(r[1]), "=r"(r[2]), "=r"(r[3]) : "r"(addr));
}
__device__ __forceinline__ void mma16816(float* d, const uint32_t* a, uint32_t b0, uint32_t b1) {
    asm volatile("mma.sync.aligned.m16n8k16.row.col.f32.bf16.bf16.f32 "
                 "{%0,%1,%2,%3}, {%4,%5,%6,%7}, {%8,%9}, {%0,%1,%2,%3};"
                 : "+f"(d[0]), "+f"(d[1]), "+f"(d[2]), "+f"(d[3])
                 : "r"(a[0]), "r"(a[1]), "r"(a[2]), "r"(a[3]), "r"(b0), "r"(b1));
}
__device__ __forceinline__ void split_pack(float2 v, uint32_t& hi, uint32_t& lo) {
    __nv_bfloat16 hx = __float2bfloat16(v.x), hy = __float2bfloat16(v.y);
    __nv_bfloat16 lx = __float2bfloat16(v.x - __bfloat162float(hx));
    __nv_bfloat16 ly = __float2bfloat16(v.y - __bfloat162float(hy));
    hi = ((uint32_t)__bfloat16_as_ushort(hy) << 16) | __bfloat16_as_ushort(hx);
    lo = ((uint32_t)__bfloat16_as_ushort(ly) << 16) | __bfloat16_as_ushort(lx);
}

// ---------------- hi/lo conversion (emb, Wih only) ----------------
__global__ void cvt_hilo(const float* __restrict__ src, int sel, size_t n)
{
    __nv_bfloat16 *hi, *lo;
    if (sel == 0) { hi = g_embh; lo = g_embl; }
    else          { hi = g_wihh; lo = g_wihl; }
    size_t stride = (size_t)gridDim.x * blockDim.x * 4;
    for (size_t v = ((size_t)blockIdx.x * blockDim.x + threadIdx.x) * 4; v < n; v += stride) {
        float4 f = *(const float4*)(src + v);
        __nv_bfloat16 h0 = __float2bfloat16(f.x), h1 = __float2bfloat16(f.y);
        __nv_bfloat16 h2 = __float2bfloat16(f.z), h3 = __float2bfloat16(f.w);
        __nv_bfloat16 l0 = __float2bfloat16(f.x - __bfloat162float(h0));
        __nv_bfloat16 l1 = __float2bfloat16(f.y - __bfloat162float(h1));
        __nv_bfloat16 l2 = __float2bfloat16(f.z - __bfloat162float(h2));
        __nv_bfloat16 l3 = __float2bfloat16(f.w - __bfloat162float(h3));
        *(__nv_bfloat162*)(hi + v)     = __halves2bfloat162(h0, h1);
        *(__nv_bfloat162*)(hi + v + 2) = __halves2bfloat162(h2, h3);
        *(__nv_bfloat162*)(lo + v)     = __halves2bfloat162(l0, l1);
        *(__nv_bfloat162*)(lo + v + 2) = __halves2bfloat162(l2, l3);
    }
}

// ---------------- warp-MMA input-projection GEMM (bf16x3, unchanged) ----------------
__global__ void __launch_bounds__(256, 1) gemm_mma(
    const int* __restrict__ x, const float* __restrict__ bi,
    const float* __restrict__ bh, int use_gather, int layer)
{
    extern __shared__ __align__(128) char smem[];
    const __nv_bfloat16** rp_hi = (const __nv_bfloat16**)(smem + OFF_CTRL);
    const __nv_bfloat16** rp_lo = (const __nv_bfloat16**)(smem + OFF_CTRL + 1024);
    float* biassh = (float*)(smem + OFF_CTRL + 2048);

    int tid = threadIdx.x, wid = tid >> 5, lane = tid & 31;
    int n0 = blockIdx.x * GN, m0 = blockIdx.y * GM;
    uint32_t sb = smem_u32(smem);

    const __nv_bfloat16* ah = use_gather ? g_embh : g_hsh;
    const __nv_bfloat16* al = use_gather ? g_embl : g_hsl;
    const __nv_bfloat16* whi = g_wihh + (size_t)layer * GG * HH;
    const __nv_bfloat16* wlo = g_wihl + (size_t)layer * GG * HH;

    if (tid < 128) {
        int mg = m0 + tid;
        size_t rowoff;
        if (use_gather) {
            int t = mg >> 5, b = mg & 31;
            rowoff = (size_t)x[b * TT + t] * HH;
        } else {
            rowoff = (size_t)mg * HH;
        }
        rp_hi[tid] = ah + rowoff;
        rp_lo[tid] = al + rowoff;
        biassh[tid] = bi[n0 + tid] + bh[n0 + tid];
    }
    __syncthreads();

    auto load_chunk = [&](int c, int s) {
        uint32_t base = sb + s * STAGE;
        const __nv_bfloat16* w_h = whi + (size_t)n0 * HH + c * KC;
        const __nv_bfloat16* w_l = wlo + (size_t)n0 * HH + c * KC;
#pragma unroll
        for (int it = 0; it < 4; ++it) {
            int task = it * 256 + tid;
            int row = task >> 3, q = task & 7;
            uint32_t off = row * RSB + q * 16;
            cpa16(base + OFF_A_HI + off, (const char*)(rp_hi[row] + c * KC) + q * 16);
            cpa16(base + OFF_A_LO + off, (const char*)(rp_lo[row] + c * KC) + q * 16);
            cpa16(base + OFF_B_HI + off, (const char*)(w_h + (size_t)row * HH) + q * 16);
            cpa16(base + OFF_B_LO + off, (const char*)(w_l + (size_t)row * HH) + q * 16);
        }
    };

    int wm = wid >> 1, wn = wid & 1;
    int m0w = wm * 32, n0w = wn * 64;

    float acc[64];
#pragma unroll
    for (int i = 0; i < 64; ++i) acc[i] = 0.f;

    load_chunk(0, 0);
    cpa_commit();

    for (int c = 0; c < 8; ++c) {
        if (c < 7) {
            load_chunk(c + 1, (c + 1) & 1);
            cpa_commit();
            cpa_wait<1>();
        } else {
            cpa_wait<0>();
        }
        __syncthreads();

        uint32_t sbase = sb + (c & 1) * STAGE;
#pragma unroll
        for (int ks = 0; ks < 4; ++ks) {
            uint32_t a_h[2][4], a_l[2][4];
#pragma unroll
            for (int mt = 0; mt < 2; ++mt) {
                uint32_t row = m0w + mt * 16 + (lane & 15);
                uint32_t kb = ks * 32 + (lane >> 4) * 16;
                ldsm4(a_h[mt], sbase + OFF_A_HI + row * RSB + kb);
                ldsm4(a_l[mt], sbase + OFF_A_LO + row * RSB + kb);
            }
            uint32_t b_h[4][4], b_l[4][4];
#pragma unroll
            for (int p = 0; p < 4; ++p) {
                uint32_t row = n0w + p * 16 + ((lane >> 4) << 3) + (lane & 7);
                uint32_t kb = ks * 32 + ((lane >> 3) & 1) * 16;
                ldsm4(b_h[p], sbase + OFF_B_HI + row * RSB + kb);
                ldsm4(b_l[p], sbase + OFF_B_LO + row * RSB + kb);
            }
#pragma unroll
            for (int mt = 0; mt < 2; ++mt)
#pragma unroll
                for (int p = 0; p < 4; ++p)
#pragma unroll
                    for (int h = 0; h < 2; ++h) {
                        float* d = &acc[(mt * 8 + p * 2 + h) * 4];
                        mma16816(d, a_h[mt], b_h[p][2 * h], b_h[p][2 * h + 1]);
                        mma16816(d, a_h[mt], b_l[p][2 * h], b_l[p][2 * h + 1]);
                        mma16816(d, a_l[mt], b_h[p][2 * h], b_h[p][2 * h + 1]);
                    }
        }
        __syncthreads();
    }

    float* Cs = (float*)smem;   // [128][129]
#pragma unroll
    for (int mt = 0; mt < 2; ++mt)
#pragma unroll
        for (int nt = 0; nt < 8; ++nt) {
            const float* d = &acc[(mt * 8 + nt) * 4];
            int r0 = m0w + mt * 16 + (lane >> 2);
            int c0 = n0w + nt * 8 + 2 * (lane & 3);
            Cs[r0 * 129 + c0]           = d[0];
            Cs[r0 * 129 + c0 + 1]       = d[1];
            Cs[(r0 + 8) * 129 + c0]     = d[2];
            Cs[(r0 + 8) * 129 + c0 + 1] = d[3];
        }
    __syncthreads();

#pragma unroll
    for (int it = 0; it < 2; ++it) {
        int task = it * 256 + tid;
        int tl = task >> 7, n = task & 127;
        float bias = biassh[n];
        int t = (m0 >> 5) + tl;
        int ng = n0 + n;
        float* dst = &g_ix[((size_t)t * GG + ng) * BB];
#pragma unroll
        for (int bq = 0; bq < 8; ++bq) {
            float4 v;
            v.x = Cs[(tl * 32 + bq * 4 + 0) * 129 + n] + bias;
            v.y = Cs[(tl * 32 + bq * 4 + 1) * 129 + n] + bias;
            v.z = Cs[(tl * 32 + bq * 4 + 2) * 129 + n] + bias;
            v.w = Cs[(tl * 32 + bq * 4 + 3) * 129 + n] + bias;
            *(float4*)(dst + bq * 4) = v;
        }
    }
}

// ---------------- tensor-core persistent recurrence (epoch-stamped exchange) ----------------
// CTA (j,i): batches [8j,8j+8), units [16i,16i+16). 8 warps, warp w owns k-slice 64.
// h exchange: uint4 (hi, epoch, lo, epoch). Consumer poll IS the load (no flags).
// red[] parity double-buffered; one __syncthreads per step.
__global__ __launch_bounds__(RT, 1) void recur_mma(const float* __restrict__ Whh, int layer)
{
    __shared__ float red[2][8 * 64 * 8];  // [par][w][row64][b8] 32KB
    __shared__ float csh[128];

    int tid = threadIdx.x;
    int lane = tid & 31, w = tid >> 5;
    int gid = lane >> 2, tig = lane & 3;
    int j = blockIdx.x >> 5;          // column
    int i = blockIdx.x & 31;          // row-group
    int U0 = i * NU, B0 = j * BPC;

    // ---- prologue: Whh A-fragments (bf16 hi/lo) into registers ----
    uint32_t Ah[4][4][4], Al[4][4][4];
#pragma unroll
    for (int g = 0; g < 4; ++g) {
        const float* r0 = Whh + (size_t)(g * HH + U0 + gid) * HH;
        const float* r8 = r0 + (size_t)8 * HH;
#pragma unroll
        for (int ksl = 0; ksl < 4; ++ksl) {
            int k = (w * 4 + ksl) * 16 + tig * 2;
            split_pack(*(const float2*)(r0 + k),     Ah[g][ksl][0], Al[g][ksl][0]);
            split_pack(*(const float2*)(r8 + k),     Ah[g][ksl][1], Al[g][ksl][1]);
            split_pack(*(const float2*)(r0 + k + 8), Ah[g][ksl][2], Al[g][ksl][2]);
            split_pack(*(const float2*)(r8 + k + 8), Ah[g][ksl][3], Al[g][ksl][3]);
        }
    }
    if (tid < 128) csh[tid] = 0.f;
    __syncthreads();

    int cu = tid >> 3, cb = tid & 7;                    // cell identity (tid<128)
    int bw = w * 256 + lane;                            // fragment base (uint4 units)

    // producer word index: k = U0+cu -> m = k>>1
    int pk = U0 + cu;
    int pm = pk >> 1;
    int pW = (((pm >> 5) * 8) + (((pm >> 3) & 3) * 2) + ((pm >> 2) & 1)) * 32 + cb * 4 + (pm & 3);
    int phalf = pk & 1;

    for (int t = 0; t < TT; ++t) {
        float ixv[4];
        if (tid < 128) {
#pragma unroll
            for (int g = 0; g < 4; ++g)
                ixv[g] = g_ix[((size_t)t * GG + g * HH + U0 + cu) * BB + B0 + cb];
        }

        // data-poll: detect == load. Dual epoch defeats 8B tearing.
        int par = t & 1;
        uint32_t tgt = (uint32_t)(t + 1);
        const uint4* hp = &g_hf4[layer][par][j][0];
        uint4 a0[4], a1[4];
        for (;;) {
            bool ok = true;
#pragma unroll
            for (int ksl = 0; ksl < 4; ++ksl) {
                a0[ksl] = ldv4(hp + bw + ksl * 64);
                a1[ksl] = ldv4(hp + bw + ksl * 64 + 32);
            }
#pragma unroll
            for (int ksl = 0; ksl < 4; ++ksl)
                ok &= (a0[ksl].y == tgt) & (a0[ksl].w == tgt)
                    & (a1[ksl].y == tgt) & (a1[ksl].w == tgt);
            if (__all_sync(0xFFFFFFFFu, ok)) break;
        }

        float d0[4], d1[4], d2[4], d3[4];
#pragma unroll
        for (int q = 0; q < 4; ++q) { d0[q] = 0.f; d1[q] = 0.f; d2[q] = 0.f; d3[q] = 0.f; }

#pragma unroll
        for (int ksl = 0; ksl < 4; ++ksl) {
            uint32_t b0h = a0[ksl].x, b0l = a0[ksl].z;
            uint32_t b1h = a1[ksl].x, b1l = a1[ksl].z;
            mma16816(d0, Ah[0][ksl], b0h, b1h);
            mma16816(d1, Ah[1][ksl], b0h, b1h);
            mma16816(d2, Ah[2][ksl], b0h, b1h);
            mma16816(d3, Ah[3][ksl], b0h, b1h);
            mma16816(d0, Ah[0][ksl], b0l, b1l);
            mma16816(d1, Ah[1][ksl], b0l, b1l);
            mma16816(d2, Ah[2][ksl], b0l, b1l);
            mma16816(d3, Ah[3][ksl], b0l, b1l);
            mma16816(d0, Al[0][ksl], b0h, b1h);
            mma16816(d1, Al[1][ksl], b0h, b1h);
            mma16816(d2, Al[2][ksl], b0h, b1h);
            mma16816(d3, Al[3][ksl], b0h, b1h);
        }
        // partials -> red[par]: STS.64, linear in lane
        {
            float2* r64 = (float2*)red[par];
            int base = w * 256;
            r64[base + 0 * 64 + lane]      = make_float2(d0[0], d0[1]);
            r64[base + 0 * 64 + 32 + lane] = make_float2(d0[2], d0[3]);
            r64[base + 1 * 64 + lane]      = make_float2(d1[0], d1[1]);
            r64[base + 1 * 64 + 32 + lane] = make_float2(d1[2], d1[3]);
            r64[base + 2 * 64 + lane]      = make_float2(d2[0], d2[1]);
            r64[base + 2 * 64 + 32 + lane] = make_float2(d2[2], d2[3]);
            r64[base + 3 * 64 + lane]      = make_float2(d3[0], d3[1]);
            r64[base + 3 * 64 + 32 + lane] = make_float2(d3[2], d3[3]);
        }
        __syncthreads();   // single barrier per step (RAW on partials; bounds skew <=1)

        if (tid < 128) {
            const float* rp = red[par];
            float gate[4];
#pragma unroll
            for (int g = 0; g < 4; ++g) {
                float s = ixv[g];
                int ro = (g * 16 + cu) * 8 + cb;
#pragma unroll
                for (int ww = 0; ww < 8; ++ww)
                    s += rp[ww * 512 + ro];
                gate[g] = s;
            }
            float si = fast_sigmoid(gate[0]);
            float sf = fast_sigmoid(gate[1]);
            float gg = fast_tanh(gate[2]);
            float so = fast_sigmoid(gate[3]);
            float c  = sf * csh[tid] + si * gg;
            float h  = so * fast_tanh(c);

            // shuffle-pack with partner (tid^8 holds the other k of the pair)
            __nv_bfloat16 hh = __float2bfloat16(h);
            __nv_bfloat16 hl = __float2bfloat16(h - __bfloat162float(hh));
            uint32_t mypack = (uint32_t)__bfloat16_as_ushort(hh)
                            | ((uint32_t)__bfloat16_as_ushort(hl) << 16);
            uint32_t ppack = __shfl_xor_sync(0xFFFFFFFFu, mypack, 8);
            if (phalf == 0) {
                uint32_t hi_word = (mypack & 0xFFFFu) | (ppack << 16);
                uint32_t lo_word = (mypack >> 16) | (ppack & 0xFFFF0000u);
                uint4 v = make_uint4(hi_word, (uint32_t)(t + 2), lo_word, (uint32_t)(t + 2));
                stv4(&g_hf4[layer][(t + 1) & 1][j][pW], v);
            }

            csh[tid] = c;
            int bg = B0 + cb;
            if (layer == 0) {
                g_hsh[((size_t)t * BB + bg) * HH + pk] = hh;
                g_hsl[((size_t)t * BB + bg) * HH + pk] = hl;
            } else if (t == TT - 1) {
                g_hs[((size_t)t * BB + bg) * HH + pk] = h;
            }
        }
    }
}

// ---------------- head ----------------
__global__ void head_kernel(const float* __restrict__ fcw, const float* __restrict__ fcb,
                            const int* __restrict__ labels, float* __restrict__ out, int out_size)
{
    __shared__ float lg[128];
    __shared__ float pl[32];
    int tid = threadIdx.x;
    int b = tid >> 2, c = tid & 3;
    const float* h = g_hs + ((size_t)(TT - 1) * BB + b) * HH;
    const float* wr = fcw + c * HH;
    float acc = 0.f;
#pragma unroll 8
    for (int k = 0; k < HH; k += 4) {
        float4 hv = *(const float4*)(h + k);
        float4 wv = *(const float4*)(wr + k);
        acc += hv.x * wv.x + hv.y * wv.y + hv.z * wv.z + hv.w * wv.w;
    }
    lg[b * 4 + c] = acc + fcb[c];
    __syncthreads();
    if (tid < 32) {
        float l0 = lg[tid * 4], l1 = lg[tid * 4 + 1], l2 = lg[tid * 4 + 2], l3 = lg[tid * 4 + 3];
        float m = fmaxf(fmaxf(l0, l1), fmaxf(l2, l3));
        float lse = m + logf(expf(l0 - m) + expf(l1 - m) + expf(l2 - m) + expf(l3 - m));
        int lab = labels[tid];
        pl[tid] = lg[tid * 4 + lab] - lse;
    }
    __syncthreads();
    if (tid == 0) {
        float s = 0.f;
        for (int i = 0; i < 32; i++) s += pl[i];
        float loss = -s / 32.f;
        if (out_size == 128) {
            for (int i = 0; i < 128; i++) out[i] = lg[i];
        } else {
            out[0] = loss;
            int n = out_size - 1; if (n > 128) n = 128;
            for (int i = 0; i < n; i++) out[1 + i] = lg[i];
            for (int i = 129; i < out_size; i++) out[i] = 0.f;
        }
    }
}

__global__ void init_kernel() {
    int idx = blockIdx.x * blockDim.x + threadIdx.x;
    int total = 2 * 2 * NCOL * 2048;   // uint4 words in g_hf4
    uint4* ph = &g_hf4[0][0][0][0];
    for (int v = idx; v < total; v += gridDim.x * blockDim.x) {
        // slot par=0 (v's par bit): epoch 1 (h for t=0, zeros); slot par=1: epoch 0
        int par = (v / (NCOL * 2048)) & 1;
        uint32_t ep = (par == 0) ? 1u : 0u;
        ph[v] = make_uint4(0u, ep, 0u, ep);
    }
}

// ---------------- launch ----------------
extern "C" void kernel_launch(void* const* d_in, const int* in_sizes, int n_in,
                              void* d_out, int out_size)
{
    const int*   x      = (const int*)d_in[0];
    const int*   labels = (const int*)d_in[1];
    const float* emb    = (const float*)d_in[2];
    const float* Wih    = (const float*)d_in[3];
    const float* Whh    = (const float*)d_in[4];
    const float* bih    = (const float*)d_in[5];
    const float* bhh    = (const float*)d_in[6];
    const float* fcw    = (const float*)d_in[7];
    const float* fcb    = (const float*)d_in[8];
    float* out = (float*)d_out;

    cudaFuncSetAttribute(gemm_mma, cudaFuncAttributeMaxDynamicSharedMemorySize, GSMEM);

    init_kernel<<<64, 256>>>();
    cvt_hilo<<<1024, 256>>>(emb, 0, (size_t)VOCAB * HH);
    cvt_hilo<<<256, 256>>>(Wih, 1, (size_t)2 * GG * HH);

    dim3 gg(GG / GN, (TT * BB) / GM);   // (16, 512)
    // layer 0
    gemm_mma<<<gg, 256, GSMEM>>>(x, bih, bhh, 1, 0);
    recur_mma<<<NCOL * NRG, RT>>>(Whh, 0);
    // layer 1
    gemm_mma<<<gg, 256, GSMEM>>>(x, bih + GG, bhh + GG, 0, 1);
    recur_mma<<<NCOL * NRG, RT>>>(Whh + (size_t)GG * HH, 1);
    head_kernel<<<1, 128>>>(fcw, fcb, labels, out, out_size);
}